// round 1
// baseline (speedup 1.0000x reference)
#include <cuda_runtime.h>

#define NTH 256
#define TB 32

constexpr int NH = 100;     // hidden
constexpr int NHP = 104;    // padded row stride for W2/W1 tiles (16B-aligned float4, zero-padded)
constexpr int KD = 64;      // k per dim
constexpr int DIMS = 8;
constexpr int TOT = 512;    // DIM*K

// shared memory layout (float offsets)
constexpr int OFF_W2S  = 0;                 // [100][104]
constexpr int OFF_W2T  = 10400;             // [100][104]
constexpr int OFF_W3S  = 20800;             // [100][64]
constexpr int OFF_W3T  = 27200;             // [100][64]
constexpr int OFF_ACCS = 33600;             // [100][32]
constexpr int OFF_ACCT = 36800;             // [100][32]
constexpr int OFF_SV   = 40000;             // [64][32] sigmoid(s)
constexpr int OFF_ZB   = 42048;             // [64][32] z tile
constexpr int OFF_LD   = 44096;             // [32] log_det accum
constexpr int OFF_SB1  = 44128;
constexpr int OFF_SB2  = 44228;
constexpr int OFF_SB3  = 44328;
constexpr int OFF_TB1  = 44392;
constexpr int OFF_TB2  = 44492;
constexpr int OFF_TB3  = 44592;             // ends 44656
constexpr int OFF_SCR  = 44672;             // scratch: h1 [100][32] / Wstage [64][104]
constexpr int OFF_H2   = OFF_SCR + 3328;    // h2 [100][32] (overlaps Wstage tail; temporally disjoint)
constexpr int SMEM_FLOATS = OFF_SCR + 6656; // 51328 floats = 205312 bytes

__device__ __forceinline__ float sigm(float x) { return 1.0f / (1.0f + __expf(-x)); }

__global__ void __launch_bounds__(NTH, 1) flow_kernel(
    const float* __restrict__ e,
    const float* __restrict__ sW1, const float* __restrict__ sb1,
    const float* __restrict__ sW2, const float* __restrict__ sb2,
    const float* __restrict__ sW3, const float* __restrict__ sb3,
    const float* __restrict__ tW1, const float* __restrict__ tb1,
    const float* __restrict__ tW2, const float* __restrict__ tb2,
    const float* __restrict__ tW3, const float* __restrict__ tb3,
    float* __restrict__ zout, float* __restrict__ ldout)
{
    extern __shared__ float sm[];
    const int tid = threadIdx.x;
    const long rowBase = (long)blockIdx.x * TB;

    // ---- preload step-invariant weights / biases; zero accumulators ----
    for (int idx = tid; idx < 10400; idx += NTH) {
        int m = idx / NHP, n = idx - m * NHP;
        float vs = 0.f, vt = 0.f;
        if (n < NH) { vs = sW2[m * NH + n]; vt = tW2[m * NH + n]; }
        sm[OFF_W2S + idx] = vs;
        sm[OFF_W2T + idx] = vt;
    }
    for (int idx = tid; idx < 6400; idx += NTH) {
        sm[OFF_W3S + idx] = sW3[idx];
        sm[OFF_W3T + idx] = tW3[idx];
    }
    for (int idx = tid; idx < NH; idx += NTH) {
        sm[OFF_SB1 + idx] = sb1[idx]; sm[OFF_SB2 + idx] = sb2[idx];
        sm[OFF_TB1 + idx] = tb1[idx]; sm[OFF_TB2 + idx] = tb2[idx];
    }
    for (int idx = tid; idx < KD; idx += NTH) {
        sm[OFF_SB3 + idx] = sb3[idx]; sm[OFF_TB3 + idx] = tb3[idx];
    }
    for (int idx = tid; idx < 3200; idx += NTH) {
        sm[OFF_ACCS + idx] = 0.f; sm[OFF_ACCT + idx] = 0.f;
    }
    if (tid < TB) sm[OFF_LD + tid] = 0.f;
    __syncthreads();

    float* h1  = sm + OFF_SCR;
    float* h2  = sm + OFF_H2;
    float* Wst = sm + OFF_SCR;

    const int gi = tid >> 3;        // column-group index
    const int r0 = (tid & 7) * 4;   // row offset within 32-row tile

    for (int i = 0; i < DIMS; i++) {
        // ================= s-MLP =================
        // h1 = relu(accS + b1)
        for (int idx = tid; idx < 3200; idx += NTH) {
            float v = sm[OFF_ACCS + idx] + sm[OFF_SB1 + (idx >> 5)];
            h1[idx] = fmaxf(v, 0.f);
        }
        __syncthreads();
        // h2 = relu(W2s^T h1 + b2) : [100 x 32], 4n x 4r register tiles
        if (tid < 200) {
            const int n0 = gi * 4;
            float c[4][4];
            #pragma unroll
            for (int j = 0; j < 4; j++)
                #pragma unroll
                for (int l = 0; l < 4; l++) c[j][l] = 0.f;
            #pragma unroll 2
            for (int m = 0; m < NH; m++) {
                float4 av = *(const float4*)&h1[m * 32 + r0];
                float4 wv = *(const float4*)&sm[OFF_W2S + m * NHP + n0];
                float aa[4] = {av.x, av.y, av.z, av.w};
                float ww[4] = {wv.x, wv.y, wv.z, wv.w};
                #pragma unroll
                for (int j = 0; j < 4; j++)
                    #pragma unroll
                    for (int l = 0; l < 4; l++) c[j][l] += ww[j] * aa[l];
            }
            #pragma unroll
            for (int j = 0; j < 4; j++) {
                float b = sm[OFF_SB2 + n0 + j];
                #pragma unroll
                for (int l = 0; l < 4; l++)
                    h2[(n0 + j) * 32 + r0 + l] = fmaxf(c[j][l] + b, 0.f);
            }
        }
        __syncthreads();
        // sv = sigmoid(W3s^T h2 + b3) : [64 x 32]
        if (tid < 128) {
            const int k0 = gi * 4;
            float c[4][4];
            #pragma unroll
            for (int j = 0; j < 4; j++)
                #pragma unroll
                for (int l = 0; l < 4; l++) c[j][l] = 0.f;
            #pragma unroll 2
            for (int m = 0; m < NH; m++) {
                float4 av = *(const float4*)&h2[m * 32 + r0];
                float4 wv = *(const float4*)&sm[OFF_W3S + m * 64 + k0];
                float aa[4] = {av.x, av.y, av.z, av.w};
                float ww[4] = {wv.x, wv.y, wv.z, wv.w};
                #pragma unroll
                for (int j = 0; j < 4; j++)
                    #pragma unroll
                    for (int l = 0; l < 4; l++) c[j][l] += ww[j] * aa[l];
            }
            #pragma unroll
            for (int j = 0; j < 4; j++) {
                float b = sm[OFF_SB3 + k0 + j];
                #pragma unroll
                for (int l = 0; l < 4; l++)
                    sm[OFF_SV + (k0 + j) * 32 + r0 + l] = sigm(c[j][l] + b);
            }
        }
        __syncthreads();
        // log_det accumulation (runs concurrently with t-MLP h1 phase below)
        if (tid < TB) {
            float s = 0.f;
            #pragma unroll 8
            for (int k = 0; k < KD; k++) s += sm[OFF_SV + k * 32 + tid];
            sm[OFF_LD + tid] += s;
        }
        // ================= t-MLP =================
        for (int idx = tid; idx < 3200; idx += NTH) {
            float v = sm[OFF_ACCT + idx] + sm[OFF_TB1 + (idx >> 5)];
            h1[idx] = fmaxf(v, 0.f);
        }
        __syncthreads();
        if (tid < 200) {
            const int n0 = gi * 4;
            float c[4][4];
            #pragma unroll
            for (int j = 0; j < 4; j++)
                #pragma unroll
                for (int l = 0; l < 4; l++) c[j][l] = 0.f;
            #pragma unroll 2
            for (int m = 0; m < NH; m++) {
                float4 av = *(const float4*)&h1[m * 32 + r0];
                float4 wv = *(const float4*)&sm[OFF_W2T + m * NHP + n0];
                float aa[4] = {av.x, av.y, av.z, av.w};
                float ww[4] = {wv.x, wv.y, wv.z, wv.w};
                #pragma unroll
                for (int j = 0; j < 4; j++)
                    #pragma unroll
                    for (int l = 0; l < 4; l++) c[j][l] += ww[j] * aa[l];
            }
            #pragma unroll
            for (int j = 0; j < 4; j++) {
                float b = sm[OFF_TB2 + n0 + j];
                #pragma unroll
                for (int l = 0; l < 4; l++)
                    h2[(n0 + j) * 32 + r0 + l] = fmaxf(c[j][l] + b, 0.f);
            }
        }
        __syncthreads();
        // t = sigmoid(W3t^T h2 + b3t); z = exp(sv)*e + t; write out + zb tile
        if (tid < 128) {
            const int k0 = gi * 4;
            float c[4][4];
            #pragma unroll
            for (int j = 0; j < 4; j++)
                #pragma unroll
                for (int l = 0; l < 4; l++) c[j][l] = 0.f;
            #pragma unroll 2
            for (int m = 0; m < NH; m++) {
                float4 av = *(const float4*)&h2[m * 32 + r0];
                float4 wv = *(const float4*)&sm[OFF_W3T + m * 64 + k0];
                float aa[4] = {av.x, av.y, av.z, av.w};
                float ww[4] = {wv.x, wv.y, wv.z, wv.w};
                #pragma unroll
                for (int j = 0; j < 4; j++)
                    #pragma unroll
                    for (int l = 0; l < 4; l++) c[j][l] += ww[j] * aa[l];
            }
            const float b0 = sm[OFF_TB3 + k0 + 0];
            const float b1v = sm[OFF_TB3 + k0 + 1];
            const float b2v = sm[OFF_TB3 + k0 + 2];
            const float b3v = sm[OFF_TB3 + k0 + 3];
            #pragma unroll
            for (int l = 0; l < 4; l++) {
                const int r = r0 + l;
                const long grow = rowBase + r;
                const float4 e4 = *(const float4*)&e[grow * TOT + i * KD + k0];
                float ex0 = __expf(sm[OFF_SV + (k0 + 0) * 32 + r]);
                float ex1 = __expf(sm[OFF_SV + (k0 + 1) * 32 + r]);
                float ex2 = __expf(sm[OFF_SV + (k0 + 2) * 32 + r]);
                float ex3 = __expf(sm[OFF_SV + (k0 + 3) * 32 + r]);
                float4 zv;
                zv.x = ex0 * e4.x + sigm(c[0][l] + b0);
                zv.y = ex1 * e4.y + sigm(c[1][l] + b1v);
                zv.z = ex2 * e4.z + sigm(c[2][l] + b2v);
                zv.w = ex3 * e4.w + sigm(c[3][l] + b3v);
                *(float4*)&zout[grow * TOT + i * KD + k0] = zv;
                sm[OFF_ZB + (k0 + 0) * 32 + r] = zv.x;
                sm[OFF_ZB + (k0 + 1) * 32 + r] = zv.y;
                sm[OFF_ZB + (k0 + 2) * 32 + r] = zv.z;
                sm[OFF_ZB + (k0 + 3) * 32 + r] = zv.w;
            }
        }
        __syncthreads();

        // ======== incremental layer-1 accumulator update (skip on last step) ========
        if (i < DIMS - 1) {
            // stage sW1 slice [64][100] -> Wst[64][104] zero-padded
            for (int idx = tid; idx < 64 * NHP; idx += NTH) {
                int kk = idx / NHP, n = idx - kk * NHP;
                Wst[idx] = (n < NH) ? sW1[(i * KD + kk) * NH + n] : 0.f;
            }
            __syncthreads();
            if (tid < 200) {
                const int n0 = gi * 4;
                float c[4][4];
                #pragma unroll
                for (int j = 0; j < 4; j++)
                    #pragma unroll
                    for (int l = 0; l < 4; l++)
                        c[j][l] = sm[OFF_ACCS + (n0 + j) * 32 + r0 + l];
                #pragma unroll 2
                for (int kk = 0; kk < KD; kk++) {
                    float4 av = *(const float4*)&sm[OFF_ZB + kk * 32 + r0];
                    float4 wv = *(const float4*)&Wst[kk * NHP + n0];
                    float aa[4] = {av.x, av.y, av.z, av.w};
                    float ww[4] = {wv.x, wv.y, wv.z, wv.w};
                    #pragma unroll
                    for (int j = 0; j < 4; j++)
                        #pragma unroll
                        for (int l = 0; l < 4; l++) c[j][l] += ww[j] * aa[l];
                }
                #pragma unroll
                for (int j = 0; j < 4; j++)
                    #pragma unroll
                    for (int l = 0; l < 4; l++)
                        sm[OFF_ACCS + (n0 + j) * 32 + r0 + l] = c[j][l];
            }
            __syncthreads();
            for (int idx = tid; idx < 64 * NHP; idx += NTH) {
                int kk = idx / NHP, n = idx - kk * NHP;
                Wst[idx] = (n < NH) ? tW1[(i * KD + kk) * NH + n] : 0.f;
            }
            __syncthreads();
            if (tid < 200) {
                const int n0 = gi * 4;
                float c[4][4];
                #pragma unroll
                for (int j = 0; j < 4; j++)
                    #pragma unroll
                    for (int l = 0; l < 4; l++)
                        c[j][l] = sm[OFF_ACCT + (n0 + j) * 32 + r0 + l];
                #pragma unroll 2
                for (int kk = 0; kk < KD; kk++) {
                    float4 av = *(const float4*)&sm[OFF_ZB + kk * 32 + r0];
                    float4 wv = *(const float4*)&Wst[kk * NHP + n0];
                    float aa[4] = {av.x, av.y, av.z, av.w};
                    float ww[4] = {wv.x, wv.y, wv.z, wv.w};
                    #pragma unroll
                    for (int j = 0; j < 4; j++)
                        #pragma unroll
                        for (int l = 0; l < 4; l++) c[j][l] += ww[j] * aa[l];
                }
                #pragma unroll
                for (int j = 0; j < 4; j++)
                    #pragma unroll
                    for (int l = 0; l < 4; l++)
                        sm[OFF_ACCT + (n0 + j) * 32 + r0 + l] = c[j][l];
            }
            __syncthreads();
        }
    }

    if (tid < TB) ldout[rowBase + tid] = sm[OFF_LD + tid];
}

extern "C" void kernel_launch(void* const* d_in, const int* in_sizes, int n_in,
                              void* d_out, int out_size) {
    const float* e   = (const float*)d_in[0];
    // d_in[1] = C (adjacency; strictly upper-triangular -> incremental masking is exact)
    const float* sW1 = (const float*)d_in[2];
    const float* sb1 = (const float*)d_in[3];
    const float* sW2 = (const float*)d_in[4];
    const float* sb2 = (const float*)d_in[5];
    const float* sW3 = (const float*)d_in[6];
    const float* sb3 = (const float*)d_in[7];
    const float* tW1 = (const float*)d_in[8];
    const float* tb1 = (const float*)d_in[9];
    const float* tW2 = (const float*)d_in[10];
    const float* tb2 = (const float*)d_in[11];
    const float* tW3 = (const float*)d_in[12];
    const float* tb3 = (const float*)d_in[13];

    float* out = (float*)d_out;
    const int B = in_sizes[0] / TOT;           // 65536
    float* zout  = out;
    float* ldout = out + (size_t)B * TOT;

    cudaFuncSetAttribute(flow_kernel, cudaFuncAttributeMaxDynamicSharedMemorySize,
                         SMEM_FLOATS * (int)sizeof(float));

    flow_kernel<<<B / TB, NTH, SMEM_FLOATS * sizeof(float)>>>(
        e, sW1, sb1, sW2, sb2, sW3, sb3,
        tW1, tb1, tW2, tb2, tW3, tb3,
        zout, ldout);
}

// round 2
// speedup vs baseline: 2.9800x; 2.9800x over previous
#include <cuda_runtime.h>
#include <cstdint>

#define NTH 256
constexpr int TB   = 64;     // rows per CTA
constexpr int NH   = 100;    // hidden width
constexpr int NP   = 104;    // padded hidden (13 n8-tiles / 13 k8-steps)
constexpr int KD   = 64;     // k per dim
constexpr int DIMS = 8;
constexpr int TOT  = 512;    // DIM*KD
constexpr int HS   = 108;    // h-buffer row stride (conflict-free A-frag loads)
constexpr int ZS   = 76;     // sv/z buffer row stride (conflict-free A-frag loads)
constexpr int W3ST = 72;     // W3 row stride (conflict-free B-frag loads)

// shared layout (float offsets)
constexpr int O_W2S = 0;                      // [104][104] tf32
constexpr int O_W2T = O_W2S + NP * NP;        // 10816
constexpr int O_W3S = O_W2T + NP * NP;        // 21632  [104][72] tf32
constexpr int O_W3T = O_W3S + NP * W3ST;      // 29120
constexpr int O_HB1 = O_W3T + NP * W3ST;      // 36608  [64][108] tf32 (also W1-stage [64][104])
constexpr int O_HB2 = O_HB1 + TB * HS;        // 43520  [64][108] tf32
constexpr int O_SV  = O_HB2 + TB * HS;        // 50432  [64][76]  fp32 sv, then tf32 z
constexpr int O_B1S = O_SV + TB * ZS;         // 55296
constexpr int O_B2S = O_B1S + NP;
constexpr int O_B3S = O_B2S + NP;
constexpr int O_B1T = O_B3S + KD;
constexpr int O_B2T = O_B1T + NP;
constexpr int O_B3T = O_B2T + NP;
constexpr int SMEMF = O_B3T + KD;             // 55840 floats = 223360 B

__device__ __forceinline__ float sigm(float x) { return 1.0f / (1.0f + __expf(-x)); }

__device__ __forceinline__ uint32_t f2tf(float f) {
    uint32_t r;
    asm("cvt.rna.tf32.f32 %0, %1;" : "=r"(r) : "f"(f));
    return r;
}

__device__ __forceinline__ void mma8(float* c,
                                     uint32_t a0, uint32_t a1, uint32_t a2, uint32_t a3,
                                     uint32_t b0, uint32_t b1) {
    asm volatile(
        "mma.sync.aligned.m16n8k8.row.col.f32.tf32.tf32.f32 "
        "{%0,%1,%2,%3}, {%4,%5,%6,%7}, {%8,%9}, {%0,%1,%2,%3};"
        : "+f"(c[0]), "+f"(c[1]), "+f"(c[2]), "+f"(c[3])
        : "r"(a0), "r"(a1), "r"(a2), "r"(a3), "r"(b0), "r"(b1));
}

// C[64 x N-slice] (+)= A[64 x 8*KSTEPS] @ B[8*KSTEPS x N], warp handles rows
// [mrow, mrow+16), n-tiles nbase + nt*8. A row-major (stride AS), B "col-major"
// in mma terms = stored [k][n] row-major (stride BS). Both tf32-encoded u32.
template <int KSTEPS, int NT>
__device__ __forceinline__ void gemm(const uint32_t* __restrict__ A, int AS,
                                     const uint32_t* __restrict__ B, int BS,
                                     int mrow, int nbase, int g, int t,
                                     float c[][4]) {
    const uint32_t* a0p = A + (mrow + g) * AS + t;
    const uint32_t* a1p = a0p + 8 * AS;
    const uint32_t* bp  = B + t * BS + nbase + g;
#pragma unroll 2
    for (int ks = 0; ks < KSTEPS; ks++) {
        uint32_t a0 = a0p[0], a2 = a0p[4], a1 = a1p[0], a3 = a1p[4];
#pragma unroll
        for (int nt = 0; nt < NT; nt++) {
            uint32_t b0 = bp[nt * 8], b1 = bp[4 * BS + nt * 8];
            mma8(c[nt], a0, a1, a2, a3, b0, b1);
        }
        a0p += 8; a1p += 8; bp += 8 * BS;
    }
}

// store relu(acc + bias) as tf32 into h-buffer (stride HS), frag layout:
// thread (g,t): rows mrow+g / mrow+g+8, cols nbase+nt*8+2t (+1)
__device__ __forceinline__ void store_h(const float acc[][4], int NT, int nbase,
                                        const float* __restrict__ bias,
                                        uint32_t* __restrict__ hb,
                                        int mrow, int g, int t) {
#pragma unroll
    for (int nt = 0; nt < 7; nt++) {
        if (nt >= NT) break;
        int c = nbase + nt * 8 + 2 * t;
        float2 b = *(const float2*)&bias[c];
        uint2 p0 = make_uint2(f2tf(fmaxf(acc[nt][0] + b.x, 0.f)),
                              f2tf(fmaxf(acc[nt][1] + b.y, 0.f)));
        *(uint2*)&hb[(mrow + g) * HS + c] = p0;
        uint2 p1 = make_uint2(f2tf(fmaxf(acc[nt][2] + b.x, 0.f)),
                              f2tf(fmaxf(acc[nt][3] + b.y, 0.f)));
        *(uint2*)&hb[(mrow + g + 8) * HS + c] = p1;
    }
}

__global__ void __launch_bounds__(NTH, 1) flow_mma(
    const float* __restrict__ e,
    const float* __restrict__ sW1, const float* __restrict__ sb1,
    const float* __restrict__ sW2, const float* __restrict__ sb2,
    const float* __restrict__ sW3, const float* __restrict__ sb3,
    const float* __restrict__ tW1, const float* __restrict__ tb1,
    const float* __restrict__ tW2, const float* __restrict__ tb2,
    const float* __restrict__ tW3, const float* __restrict__ tb3,
    float* __restrict__ zout, float* __restrict__ ldout)
{
    extern __shared__ float sm[];
    uint32_t* smu = (uint32_t*)sm;
    const int tid  = threadIdx.x;
    const int wid  = tid >> 5, lane = tid & 31;
    const int g    = lane >> 2, t = lane & 3;
    const int mw   = wid & 3, nw = wid >> 2;
    const int mrow = mw * 16;
    const int nb2  = nw ? 56 : 0;   // GEMM2 / GEMM1 n-base (13 tiles -> 7/6)
    const int nb3  = nw ? 32 : 0;   // GEMM3 n-base (8 tiles -> 4/4)
    const long rowBase = (long)blockIdx.x * TB;

    // ---------- preload weights (cvt to tf32) + biases ----------
    for (int idx = tid; idx < NP * NP; idx += NTH) {
        int m = idx / NP, n = idx - m * NP;
        float vs = 0.f, vt = 0.f;
        if (m < NH && n < NH) { vs = sW2[m * NH + n]; vt = tW2[m * NH + n]; }
        smu[O_W2S + idx] = f2tf(vs);
        smu[O_W2T + idx] = f2tf(vt);
    }
    for (int idx = tid; idx < NP * W3ST; idx += NTH) {
        int m = idx / W3ST, k = idx - m * W3ST;
        float vs = 0.f, vt = 0.f;
        if (m < NH && k < KD) { vs = sW3[m * KD + k]; vt = tW3[m * KD + k]; }
        smu[O_W3S + idx] = f2tf(vs);
        smu[O_W3T + idx] = f2tf(vt);
    }
    for (int idx = tid; idx < NP; idx += NTH) {
        sm[O_B1S + idx] = (idx < NH) ? sb1[idx] : 0.f;
        sm[O_B2S + idx] = (idx < NH) ? sb2[idx] : 0.f;
        sm[O_B1T + idx] = (idx < NH) ? tb1[idx] : 0.f;
        sm[O_B2T + idx] = (idx < NH) ? tb2[idx] : 0.f;
    }
    for (int idx = tid; idx < KD; idx += NTH) {
        sm[O_B3S + idx] = sb3[idx];
        sm[O_B3T + idx] = tb3[idx];
    }

    // persistent layer-1 accumulators in MMA C-fragments
    float accS[7][4], accT[7][4];
#pragma unroll
    for (int a = 0; a < 7; a++)
#pragma unroll
        for (int b = 0; b < 4; b++) { accS[a][b] = 0.f; accT[a][b] = 0.f; }
    float ldsum = 0.f;

    __syncthreads();

    for (int i = 0; i < DIMS; i++) {
        const int NT2 = nw ? 6 : 7;
        // ---- P1: h1s = relu(accS + b1s) -> HB1 ----
        store_h(accS, NT2, nb2, sm + O_B1S, smu + O_HB1, mrow, g, t);
        __syncthreads();

        // ---- P2: GEMM2-s: HB1 @ W2s -> relu+b2 -> HB2 ----
        if (nw == 0) {
            float D[7][4] = {};
            gemm<13, 7>(smu + O_HB1, HS, smu + O_W2S, NP, mrow, 0, g, t, D);
            store_h(D, 7, 0, sm + O_B2S, smu + O_HB2, mrow, g, t);
        } else {
            float D[6][4] = {};
            gemm<13, 6>(smu + O_HB1, HS, smu + O_W2S, NP, mrow, 56, g, t, D);
            store_h(D, 6, 56, sm + O_B2S, smu + O_HB2, mrow, g, t);
        }
        __syncthreads();

        // ---- P3: GEMM3-s: HB2 @ W3s -> sigmoid -> SV (fp32) ----
        {
            float D[4][4] = {};
            gemm<13, 4>(smu + O_HB2, HS, smu + O_W3S, W3ST, mrow, nb3, g, t, D);
#pragma unroll
            for (int nt = 0; nt < 4; nt++) {
                int c = nb3 + nt * 8 + 2 * t;
                float2 b = *(const float2*)&sm[O_B3S + c];
                float2 v0 = make_float2(sigm(D[nt][0] + b.x), sigm(D[nt][1] + b.y));
                *(float2*)&sm[O_SV + (mrow + g) * ZS + c] = v0;
                float2 v1 = make_float2(sigm(D[nt][2] + b.x), sigm(D[nt][3] + b.y));
                *(float2*)&sm[O_SV + (mrow + g + 8) * ZS + c] = v1;
            }
        }
        __syncthreads();

        // ---- P4: log_det accumulation + h1t -> HB1 ----
        if (tid < TB) {
            const float4* p = (const float4*)&sm[O_SV + tid * ZS];
            float s = 0.f;
#pragma unroll
            for (int q = 0; q < 16; q++) { float4 v = p[q]; s += v.x + v.y + v.z + v.w; }
            ldsum += s;
        }
        store_h(accT, NT2, nb2, sm + O_B1T, smu + O_HB1, mrow, g, t);
        __syncthreads();

        // ---- P5: GEMM2-t ----
        if (nw == 0) {
            float D[7][4] = {};
            gemm<13, 7>(smu + O_HB1, HS, smu + O_W2T, NP, mrow, 0, g, t, D);
            store_h(D, 7, 0, sm + O_B2T, smu + O_HB2, mrow, g, t);
        } else {
            float D[6][4] = {};
            gemm<13, 6>(smu + O_HB1, HS, smu + O_W2T, NP, mrow, 56, g, t, D);
            store_h(D, 6, 56, sm + O_B2T, smu + O_HB2, mrow, g, t);
        }
        __syncthreads();

        // ---- P6: GEMM3-t -> t; z = exp(sv)*e + t; STG + z(tf32) -> SV ----
        {
            float D[4][4] = {};
            gemm<13, 4>(smu + O_HB2, HS, smu + O_W3T, W3ST, mrow, nb3, g, t, D);
            const long ecol = i * KD;
#pragma unroll
            for (int nt = 0; nt < 4; nt++) {
                int c = nb3 + nt * 8 + 2 * t;
                float2 b = *(const float2*)&sm[O_B3T + c];
#pragma unroll
                for (int h = 0; h < 2; h++) {
                    int r = mrow + g + 8 * h;
                    float tv0 = sigm(D[nt][2 * h + 0] + b.x);
                    float tv1 = sigm(D[nt][2 * h + 1] + b.y);
                    float2 sv2 = *(const float2*)&sm[O_SV + r * ZS + c];
                    const float2 e2 = *(const float2*)&e[(rowBase + r) * TOT + ecol + c];
                    float z0 = __expf(sv2.x) * e2.x + tv0;
                    float z1 = __expf(sv2.y) * e2.y + tv1;
                    *(float2*)&zout[(rowBase + r) * TOT + ecol + c] = make_float2(z0, z1);
                    *(uint2*)&smu[O_SV + r * ZS + c] = make_uint2(f2tf(z0), f2tf(z1));
                }
            }
        }
        __syncthreads();

        // ---- P7: layer-1 accumulator updates: acc += z @ W1[i-slice] ----
        if (i < DIMS - 1) {
            const float* Wg = sW1 + (size_t)i * KD * NH;
            for (int idx = tid; idx < KD * NP; idx += NTH) {
                int kk = idx / NP, n = idx - kk * NP;
                smu[O_HB1 + idx] = (n < NH) ? f2tf(Wg[kk * NH + n]) : 0u;
            }
            __syncthreads();
            if (nw == 0) gemm<8, 7>(smu + O_SV, ZS, smu + O_HB1, NP, mrow, 0,  g, t, accS);
            else         gemm<8, 6>(smu + O_SV, ZS, smu + O_HB1, NP, mrow, 56, g, t, accS);
            __syncthreads();
            const float* Wg2 = tW1 + (size_t)i * KD * NH;
            for (int idx = tid; idx < KD * NP; idx += NTH) {
                int kk = idx / NP, n = idx - kk * NP;
                smu[O_HB1 + idx] = (n < NH) ? f2tf(Wg2[kk * NH + n]) : 0u;
            }
            __syncthreads();
            if (nw == 0) gemm<8, 7>(smu + O_SV, ZS, smu + O_HB1, NP, mrow, 0,  g, t, accT);
            else         gemm<8, 6>(smu + O_SV, ZS, smu + O_HB1, NP, mrow, 56, g, t, accT);
            __syncthreads();
        }
    }

    if (tid < TB) ldout[rowBase + tid] = ldsum;
}

extern "C" void kernel_launch(void* const* d_in, const int* in_sizes, int n_in,
                              void* d_out, int out_size) {
    const float* e   = (const float*)d_in[0];
    // d_in[1] = C (strictly upper-triangular DAG -> incremental layer-1 acc is exact)
    const float* sW1 = (const float*)d_in[2];
    const float* sb1 = (const float*)d_in[3];
    const float* sW2 = (const float*)d_in[4];
    const float* sb2 = (const float*)d_in[5];
    const float* sW3 = (const float*)d_in[6];
    const float* sb3 = (const float*)d_in[7];
    const float* tW1 = (const float*)d_in[8];
    const float* tb1 = (const float*)d_in[9];
    const float* tW2 = (const float*)d_in[10];
    const float* tb2 = (const float*)d_in[11];
    const float* tW3 = (const float*)d_in[12];
    const float* tb3 = (const float*)d_in[13];

    float* out = (float*)d_out;
    const int B = in_sizes[0] / TOT;
    float* zout  = out;
    float* ldout = out + (size_t)B * TOT;

    cudaFuncSetAttribute(flow_mma, cudaFuncAttributeMaxDynamicSharedMemorySize,
                         SMEMF * (int)sizeof(float));

    flow_mma<<<B / TB, NTH, SMEMF * sizeof(float)>>>(
        e, sW1, sb1, sW2, sb2, sW3, sb3,
        tW1, tb1, tW2, tb2, tW3, tb3,
        zout, ldout);
}

// round 4
// speedup vs baseline: 4.4852x; 1.5051x over previous
#include <cuda_runtime.h>
#include <cuda_bf16.h>
#include <cstdint>

#define NTH 256
constexpr int TB   = 128;
constexpr int NH   = 100;
constexpr int NPAD = 112;   // padded hidden (7 k16-steps, 14 n8-tiles)
constexpr int KD   = 64;
constexpr int DIMS = 8;
constexpr int TOT  = 512;
constexpr int WKS  = 120;   // k-stride (halves) for W2/W3/H buffers: conflict-free ldmatrix
constexpr int W1KS = 72;    // k-stride (halves) for W1 slice buffers
constexpr int SVS  = 68;    // sv row stride (floats)

// shared layout in 4B words
constexpr int O_W2S = 0;                       // [112][60w]
constexpr int O_W2T = O_W2S + NPAD * 60;       // 6720
constexpr int O_W3S = O_W2T + NPAD * 60;       // 13440 [64][60w]
constexpr int O_W3T = O_W3S + 64 * 60;         // 17280
constexpr int O_W1S = O_W3T + 64 * 60;         // 21120 [112][36w]
constexpr int O_W1T = O_W1S + NPAD * 36;       // 25152
constexpr int O_HB1 = O_W1T + NPAD * 36;       // 29184 [128][60w] (h1; cols 0..31w double as z-buffer)
constexpr int O_HB2 = O_HB1 + TB * 60;         // 36864 [128][60w]
constexpr int O_SV  = O_HB2 + TB * 60;         // 44544 [128][68] fp32
constexpr int O_LDP = O_SV + TB * SVS;         // 53248 [128][8]
constexpr int O_B1S = O_LDP + TB * 8;          // 54272
constexpr int O_B2S = O_B1S + NPAD;
constexpr int O_B3S = O_B2S + NPAD;
constexpr int O_B1T = O_B3S + KD;
constexpr int O_B2T = O_B1T + NPAD;
constexpr int O_B3T = O_B2T + NPAD;
constexpr int SMW   = O_B3T + KD;              // 54848 words = 219392 B

__device__ __forceinline__ float sigm(float x) {
    return __fdividef(1.0f, 1.0f + __expf(-x));
}

__device__ __forceinline__ uint32_t sm_u32(const void* p) {
    uint32_t a;
    asm("{ .reg .u64 t; cvta.to.shared.u64 t, %1; cvt.u32.u64 %0, t; }" : "=r"(a) : "l"(p));
    return a;
}

__device__ __forceinline__ void ldsm4(uint32_t a, uint32_t r[4]) {
    asm volatile("ldmatrix.sync.aligned.m8n8.x4.shared.b16 {%0,%1,%2,%3},[%4];"
                 : "=r"(r[0]), "=r"(r[1]), "=r"(r[2]), "=r"(r[3]) : "r"(a));
}
__device__ __forceinline__ void ldsm2(uint32_t a, uint32_t r[2]) {
    asm volatile("ldmatrix.sync.aligned.m8n8.x2.shared.b16 {%0,%1},[%2];"
                 : "=r"(r[0]), "=r"(r[1]) : "r"(a));
}

__device__ __forceinline__ void mma_bf(float* c, const uint32_t* a, uint32_t b0, uint32_t b1) {
    asm volatile(
        "mma.sync.aligned.m16n8k16.row.col.f32.bf16.bf16.f32 "
        "{%0,%1,%2,%3},{%4,%5,%6,%7},{%8,%9},{%0,%1,%2,%3};"
        : "+f"(c[0]), "+f"(c[1]), "+f"(c[2]), "+f"(c[3])
        : "r"(a[0]), "r"(a[1]), "r"(a[2]), "r"(a[3]), "r"(b0), "r"(b1));
}

// C[2 m16][NT n8] (+)= A[32 x 16*KSTEPS] @ B; A row-major bf16 stride WKS-like,
// B stored [n][k] row-major bf16 stride BKS halves. All ldmatrix-fed.
template <int KSTEPS, int NT, int BKS>
__device__ __forceinline__ void gemm(uint32_t aA0, uint32_t aA1, uint32_t bA, uint32_t bAo,
                                     float c[2][NT][4]) {
#pragma unroll
    for (int ks = 0; ks < KSTEPS; ks++) {
        uint32_t a0[4], a1[4];
        ldsm4(aA0, a0);
        ldsm4(aA1, a1);
#pragma unroll
        for (int p = 0; p < NT / 2; p++) {
            uint32_t b[4];
            ldsm4(bA + p * (16 * BKS * 2), b);
            mma_bf(c[0][2 * p],     a0, b[0], b[1]);
            mma_bf(c[1][2 * p],     a1, b[0], b[1]);
            mma_bf(c[0][2 * p + 1], a0, b[2], b[3]);
            mma_bf(c[1][2 * p + 1], a1, b[2], b[3]);
        }
        if constexpr (NT & 1) {
            uint32_t b[2];
            ldsm2(bAo, b);
            mma_bf(c[0][NT - 1], a0, b[0], b[1]);
            mma_bf(c[1][NT - 1], a1, b[0], b[1]);
        }
        aA0 += 32; aA1 += 32; bA += 32; bAo += 32;
    }
}

// relu(c + bias) -> bf16 pairs -> hb (word stride 60)
template <int NT>
__device__ __forceinline__ void store_h(const float c[2][NT][4], const float* __restrict__ bias,
                                        uint32_t* __restrict__ hb, int nb, int mrow, int g, int t) {
#pragma unroll
    for (int mt = 0; mt < 2; mt++)
#pragma unroll
        for (int nt = 0; nt < NT; nt++) {
            int cc = nb + nt * 8 + 2 * t;
            float2 b = *(const float2*)&bias[cc];
#pragma unroll
            for (int h = 0; h < 2; h++) {
                int row = mrow + mt * 16 + h * 8 + g;
                float v0 = fmaxf(c[mt][nt][2 * h + 0] + b.x, 0.f);
                float v1 = fmaxf(c[mt][nt][2 * h + 1] + b.y, 0.f);
                __nv_bfloat162 p = __floats2bfloat162_rn(v0, v1);
                hb[row * 60 + (cc >> 1)] = *(uint32_t*)&p;
            }
        }
}

// stage W1 slice [64 k][100 n] fp32 -> [112 n][72 k-stride] bf16 (pad rows pre-zeroed)
__device__ __forceinline__ void stageW1(const float* __restrict__ Wg,
                                        __nv_bfloat16* __restrict__ dst, int tid) {
#pragma unroll 1
    for (int idx = tid; idx < KD * NH; idx += NTH) {
        int kk = idx / NH, n = idx - kk * NH;
        dst[n * W1KS + kk] = __float2bfloat16(Wg[idx]);
    }
}

__global__ void __launch_bounds__(NTH, 1) flow_bf16(
    const float* __restrict__ e,
    const float* __restrict__ sW1, const float* __restrict__ sb1,
    const float* __restrict__ sW2, const float* __restrict__ sb2,
    const float* __restrict__ sW3, const float* __restrict__ sb3,
    const float* __restrict__ tW1, const float* __restrict__ tb1,
    const float* __restrict__ tW2, const float* __restrict__ tb2,
    const float* __restrict__ tW3, const float* __restrict__ tb3,
    float* __restrict__ zout, float* __restrict__ ldout)
{
    extern __shared__ float smf[];
    uint32_t* smu = (uint32_t*)smf;
    __nv_bfloat16* smh = (__nv_bfloat16*)smf;

    const int tid = threadIdx.x;
    const int lane = tid & 31, wid = tid >> 5;
    const int g = lane >> 2, t = lane & 3;
    const int mw = wid & 3, nw = wid >> 2;
    const int mrow = mw * 32;
    const int nb2 = nw * 56;   // GEMM2/GEMM1: 7 n-tiles each
    const int nb3 = nw * 32;   // GEMM3: 4 n-tiles each
    const long rowBase = (long)blockIdx.x * TB;

    // ---- preload: zero weight regions, then fill transposed bf16 ----
    for (int w = tid; w < O_HB1; w += NTH) smu[w] = 0u;
    __syncthreads();
    for (int idx = tid; idx < NH * NH; idx += NTH) {
        int in = idx / NH, out = idx - in * NH;
        smh[O_W2S * 2 + out * WKS + in] = __float2bfloat16(sW2[idx]);
        smh[O_W2T * 2 + out * WKS + in] = __float2bfloat16(tW2[idx]);
    }
    for (int idx = tid; idx < NH * KD; idx += NTH) {
        int in = idx / KD, out = idx - in * KD;
        smh[O_W3S * 2 + out * WKS + in] = __float2bfloat16(sW3[idx]);
        smh[O_W3T * 2 + out * WKS + in] = __float2bfloat16(tW3[idx]);
    }
    for (int idx = tid; idx < NPAD; idx += NTH) {
        smf[O_B1S + idx] = (idx < NH) ? sb1[idx] : 0.f;
        smf[O_B2S + idx] = (idx < NH) ? sb2[idx] : 0.f;
        smf[O_B1T + idx] = (idx < NH) ? tb1[idx] : 0.f;
        smf[O_B2T + idx] = (idx < NH) ? tb2[idx] : 0.f;
    }
    for (int idx = tid; idx < KD; idx += NTH) {
        smf[O_B3S + idx] = sb3[idx];
        smf[O_B3T + idx] = tb3[idx];
    }

    // ---- ldmatrix address precompute ----
    const uint32_t smb = sm_u32(smf);
    const int aRow = lane & 15, aK = (lane >> 4) << 3;
    const uint32_t aHB1_0 = smb + O_HB1 * 4 + ((mrow + aRow) * WKS + aK) * 2;
    const uint32_t aHB1_1 = aHB1_0 + 16 * WKS * 2;
    const uint32_t aHB2_0 = smb + O_HB2 * 4 + ((mrow + aRow) * WKS + aK) * 2;
    const uint32_t aHB2_1 = aHB2_0 + 16 * WKS * 2;
    const int bRow = (lane & 7) + ((lane >> 4) << 3);
    const int bK = ((lane >> 3) & 1) << 3;
    const int bORow = lane & 7;
    const uint32_t bW2S  = smb + O_W2S * 4 + ((nb2 + bRow) * WKS + bK) * 2;
    const uint32_t bW2So = smb + O_W2S * 4 + ((nb2 + 48 + bORow) * WKS + bK) * 2;
    const uint32_t bW2T  = smb + O_W2T * 4 + ((nb2 + bRow) * WKS + bK) * 2;
    const uint32_t bW2To = smb + O_W2T * 4 + ((nb2 + 48 + bORow) * WKS + bK) * 2;
    const uint32_t bW3S  = smb + O_W3S * 4 + ((nb3 + bRow) * WKS + bK) * 2;
    const uint32_t bW3T  = smb + O_W3T * 4 + ((nb3 + bRow) * WKS + bK) * 2;
    const uint32_t bW1S  = smb + O_W1S * 4 + ((nb2 + bRow) * W1KS + bK) * 2;
    const uint32_t bW1So = smb + O_W1S * 4 + ((nb2 + 48 + bORow) * W1KS + bK) * 2;
    const uint32_t bW1T  = smb + O_W1T * 4 + ((nb2 + bRow) * W1KS + bK) * 2;
    const uint32_t bW1To = smb + O_W1T * 4 + ((nb2 + 48 + bORow) * W1KS + bK) * 2;

    // persistent layer-1 accumulators (C-fragments) + logdet partials
    float accS[2][7][4], accT[2][7][4];
#pragma unroll
    for (int a = 0; a < 2; a++)
#pragma unroll
        for (int b = 0; b < 7; b++)
#pragma unroll
            for (int q = 0; q < 4; q++) { accS[a][b][q] = 0.f; accT[a][b][q] = 0.f; }
    float ldacc[4] = {0.f, 0.f, 0.f, 0.f};

    __syncthreads();

    for (int i = 0; i < DIMS; i++) {
        // ---- A: acc += z_{i-1} @ W1[slice i-1] (staged during step i-1), then h1s -> HB1 ----
        if (i > 0) {
            gemm<4, 7, W1KS>(aHB1_0, aHB1_1, bW1S, bW1So, accS);
            gemm<4, 7, W1KS>(aHB1_0, aHB1_1, bW1T, bW1To, accT);
            __syncthreads();
        }
        store_h<7>(accS, smf + O_B1S, smu + O_HB1, nb2, mrow, g, t);
        __syncthreads();

        // ---- B: GEMM2-s ----
        {
            float D[2][7][4] = {};
            gemm<7, 7, WKS>(aHB1_0, aHB1_1, bW2S, bW2So, D);
            store_h<7>(D, smf + O_B2S, smu + O_HB2, nb2, mrow, g, t);
        }
        __syncthreads();

        // ---- C: GEMM3-s -> sv; logdet frag-accum; h1t -> HB1; stage W1s slice i ----
        {
            float D[2][4][4] = {};
            gemm<7, 4, WKS>(aHB2_0, aHB2_1, bW3S, 0, D);
#pragma unroll
            for (int mt = 0; mt < 2; mt++)
#pragma unroll
                for (int nt = 0; nt < 4; nt++) {
                    int cc = nb3 + nt * 8 + 2 * t;
                    float2 b3 = *(const float2*)&smf[O_B3S + cc];
#pragma unroll
                    for (int h = 0; h < 2; h++) {
                        int row = mrow + mt * 16 + h * 8 + g;
                        float v0 = sigm(D[mt][nt][2 * h + 0] + b3.x);
                        float v1 = sigm(D[mt][nt][2 * h + 1] + b3.y);
                        *(float2*)&smf[O_SV + row * SVS + cc] = make_float2(v0, v1);
                        ldacc[mt * 2 + h] += v0 + v1;
                    }
                }
            store_h<7>(accT, smf + O_B1T, smu + O_HB1, nb2, mrow, g, t);
            // stage slice i: consumed by phase A of step i+1 (z_i @ W1[i*KD:(i+1)*KD])
            if (i < DIMS - 1) stageW1(sW1 + (size_t)i * KD * NH, smh + O_W1S * 2, tid);
        }
        __syncthreads();

        // ---- D: GEMM2-t; stage W1t slice i ----
        {
            float D[2][7][4] = {};
            gemm<7, 7, WKS>(aHB1_0, aHB1_1, bW2T, bW2To, D);
            store_h<7>(D, smf + O_B2T, smu + O_HB2, nb2, mrow, g, t);
            if (i < DIMS - 1) stageW1(tW1 + (size_t)i * KD * NH, smh + O_W1T * 2, tid);
        }
        __syncthreads();

        // ---- E: GEMM3-t -> t; z = exp(sv)*e + t; STG + z(bf16) -> ZB(=HB1) ----
        {
            float D[2][4][4] = {};
            gemm<7, 4, WKS>(aHB2_0, aHB2_1, bW3T, 0, D);
#pragma unroll
            for (int mt = 0; mt < 2; mt++)
#pragma unroll
                for (int nt = 0; nt < 4; nt++) {
                    int cc = nb3 + nt * 8 + 2 * t;
                    float2 b3 = *(const float2*)&smf[O_B3T + cc];
#pragma unroll
                    for (int h = 0; h < 2; h++) {
                        int row = mrow + mt * 16 + h * 8 + g;
                        float t0 = sigm(D[mt][nt][2 * h + 0] + b3.x);
                        float t1 = sigm(D[mt][nt][2 * h + 1] + b3.y);
                        float2 sv = *(const float2*)&smf[O_SV + row * SVS + cc];
                        long gidx = (rowBase + row) * TOT + i * KD + cc;
                        float2 e2 = *(const float2*)&e[gidx];
                        float z0 = __expf(sv.x) * e2.x + t0;
                        float z1 = __expf(sv.y) * e2.y + t1;
                        *(float2*)&zout[gidx] = make_float2(z0, z1);
                        __nv_bfloat162 zb = __floats2bfloat162_rn(z0, z1);
                        smu[O_HB1 + row * 60 + (cc >> 1)] = *(uint32_t*)&zb;
                    }
                }
        }
        __syncthreads();
    }

    // ---- logdet reduction: 8 partials per row ----
#pragma unroll
    for (int mt = 0; mt < 2; mt++)
#pragma unroll
        for (int h = 0; h < 2; h++) {
            int row = mrow + mt * 16 + h * 8 + g;
            smf[O_LDP + row * 8 + nw * 4 + t] = ldacc[mt * 2 + h];
        }
    __syncthreads();
    if (tid < TB) {
        float v = 0.f;
#pragma unroll
        for (int q = 0; q < 8; q++) v += smf[O_LDP + tid * 8 + q];
        ldout[rowBase + tid] = v;
    }
}

extern "C" void kernel_launch(void* const* d_in, const int* in_sizes, int n_in,
                              void* d_out, int out_size) {
    const float* e   = (const float*)d_in[0];
    // d_in[1] = C (strictly upper-triangular DAG -> incremental layer-1 acc is exact)
    const float* sW1 = (const float*)d_in[2];
    const float* sb1 = (const float*)d_in[3];
    const float* sW2 = (const float*)d_in[4];
    const float* sb2 = (const float*)d_in[5];
    const float* sW3 = (const float*)d_in[6];
    const float* sb3 = (const float*)d_in[7];
    const float* tW1 = (const float*)d_in[8];
    const float* tb1 = (const float*)d_in[9];
    const float* tW2 = (const float*)d_in[10];
    const float* tb2 = (const float*)d_in[11];
    const float* tW3 = (const float*)d_in[12];
    const float* tb3 = (const float*)d_in[13];

    float* out = (float*)d_out;
    const int B = in_sizes[0] / TOT;
    float* zout  = out;
    float* ldout = out + (size_t)B * TOT;

    cudaFuncSetAttribute(flow_bf16, cudaFuncAttributeMaxDynamicSharedMemorySize,
                         SMW * (int)sizeof(float));

    flow_bf16<<<B / TB, NTH, SMW * sizeof(float)>>>(
        e, sW1, sb1, sW2, sb2, sW3, sb3,
        tW1, tb1, tW2, tb2, tW3, tb3,
        zout, ldout);
}